// round 11
// baseline (speedup 1.0000x reference)
#include <cuda_runtime.h>
#include <cuda_fp16.h>
#include <cstdint>
#include <math.h>

#define BB 128
#define DD 512
#define TT 1024
#define GG 256
#define KK 32
#define HH 64
#define CC 4
#define CH 8          // CTAs per cluster, each owns a t-slice
#define TCH 128       // t's per CTA

// Scratch (allocation-free rule: __device__ globals)
__device__ float g_u[BB*DD];
__device__ float g_c[BB*DD];
__device__ float g_R1p[BB*CH];
__device__ float g_R2p[BB*CH];
__device__ float g_Ap[CH*BB*DD];   // per-rank A partials, 2 MB

// dynamic smem layout (bytes)
#define XOFF     0            // half x[512][128]       = 131072
#define UCOFF    131072       // float2 uc[512]         = 4096
#define REDOFF   135168       // float red[8*32*16]     = 16384
#define RSTDOFF  151552       // float rstd[128]        = 512
#define MAXOFF   152064       // float maxb[8]          = 32
#define DENOFF   152096       // float denb[8]          = 32
#define R32OFF   152128       // float r32[32]          = 128
#define SCOFF    152256       // float sSc[2]           = 8
#define SMEM_MAIN 152320

__device__ __forceinline__ float warpSum(float v) {
    #pragma unroll
    for (int o = 16; o > 0; o >>= 1) v += __shfl_xor_sync(0xffffffffu, v, o);
    return v;
}
__device__ __forceinline__ float warpMax(float v) {
    #pragma unroll
    for (int o = 16; o > 0; o >>= 1) v = fmaxf(v, __shfl_xor_sync(0xffffffffu, v, o));
    return v;
}
__device__ __forceinline__ void stc_f1(unsigned int laddr, int rank, float v) {
    unsigned int ra;
    asm volatile("mapa.shared::cluster.u32 %0, %1, %2;" : "=r"(ra) : "r"(laddr), "r"(rank));
    asm volatile("st.shared::cluster.f32 [%0], %1;" :: "r"(ra), "f"(v) : "memory");
}
#define CLUSTER_SYNC() do { \
    asm volatile("barrier.cluster.arrive.aligned;" ::: "memory"); \
    asm volatile("barrier.cluster.wait.aligned;" ::: "memory"); \
} while (0)

// ---------------------------------------------------------------------------
// Kernel 1: u/c precompute, chunk-parallel (unchanged from R10 version).
// ---------------------------------------------------------------------------
__global__ void __launch_bounds__(128) k1_prep(
        const float* __restrict__ gaf, const float* __restrict__ Wq,
        const float* __restrict__ Wkv, const float* __restrict__ Wout) {
    int chunk = blockIdx.x, b = blockIdx.y, tid = threadIdx.x;
    int w = tid >> 5, lane = tid & 31;
    __shared__ float s_gaf[GG];
    __shared__ float s_kv[KK];

    s_gaf[tid]       = gaf[b * GG + tid];
    s_gaf[tid + 128] = gaf[b * GG + tid + 128];
    __syncthreads();

    #pragma unroll
    for (int kk = 0; kk < 8; kk++) {
        int k = w * 8 + kk;
        float acc = 0.f;
        #pragma unroll
        for (int i = 0; i < 8; i++) {
            int g = lane + 32 * i;
            acc += s_gaf[g] * Wkv[k * GG + g];
        }
        acc = warpSum(acc);
        if (lane == 0) s_kv[k] = acc;
    }
    __syncthreads();

    int d = chunk * 128 + tid;
    float uu = 0.f;
    #pragma unroll
    for (int k = 0; k < KK; k++) uu += Wq[k * DD + d] * s_kv[k];
    float cc = 0.f;
    const float4* wo = (const float4*)(Wout + d * KK);
    #pragma unroll
    for (int q = 0; q < 8; q++) {
        float4 v = wo[q];
        cc += v.x * s_kv[q*4] + v.y * s_kv[q*4+1] + v.z * s_kv[q*4+2] + v.w * s_kv[q*4+3];
    }
    g_u[b * DD + d] = uu;
    g_c[b * DD + d] = cc;
}

// ---------------------------------------------------------------------------
// Fused main kernel, T-MAJOR: cluster of 8 CTAs per batch; CTA owns 128 t's
// across all 512 d. Per-t stats fully local; only softmax max/denom (2 scalars
// per CTA) cross the cluster. A-partials over local t go to gmem scratch.
// ---------------------------------------------------------------------------
__global__ void __launch_bounds__(256, 1) __cluster_dims__(CH, 1, 1)
k_main(const float* __restrict__ tcf) {
    extern __shared__ char smem[];
    uint2*  xs     = (uint2*)(smem + XOFF);       // x stash: [512][32] uint2 (4 half each)
    float2* uc     = (float2*)(smem + UCOFF);
    float*  red    = (float*)(smem + REDOFF);
    float*  rstd_s = (float*)(smem + RSTDOFF);
    float*  maxb   = (float*)(smem + MAXOFF);
    float*  denb   = (float*)(smem + DENOFF);
    float*  r32    = (float*)(smem + R32OFF);
    float*  sSc    = (float*)(smem + SCOFF);

    const int rank = blockIdx.x;      // t-slice index
    const int b    = blockIdx.y;
    const int tid  = threadIdx.x;
    const int lane = tid & 31, w = tid >> 5;   // w = warp = row-in-group

    unsigned int smem_u32 = (unsigned int)__cvta_generic_to_shared(smem);

    // u,c for ALL 512 d into smem
    #pragma unroll
    for (int it = 0; it < 2; it++) {
        int d = tid + it * 256;
        uc[d] = make_float2(g_u[b * DD + d], g_c[b * DD + d]);
    }
    __syncthreads();

    // ---- Phase 1: stream 512 rows x 128 t (own slice). Warp w reads rows
    // d = r*8+w; lane owns t-sub-range [4*lane, 4*lane+4). 512B/warp coalesced.
    const float4* xp = (const float4*)(tcf + ((size_t)b * DD + w) * TT + rank * TCH) + lane;
    float4 dot = {0,0,0,0}, s1 = {0,0,0,0}, s2 = {0,0,0,0}, sxc = {0,0,0,0};

    #pragma unroll 8
    for (int r = 0; r < 64; r++) {
        int d = r * 8 + w;
        float4 xv = xp[(size_t)r * 2048];   // 8 rows * 256 float4/row
        float2 u_ = uc[d];
        dot.x += xv.x*u_.x; dot.y += xv.y*u_.x; dot.z += xv.z*u_.x; dot.w += xv.w*u_.x;
        s1.x  += xv.x;      s1.y  += xv.y;      s1.z  += xv.z;      s1.w  += xv.w;
        s2.x  += xv.x*xv.x; s2.y  += xv.y*xv.y; s2.z  += xv.z*xv.z; s2.w  += xv.w*xv.w;
        sxc.x += xv.x*u_.y; sxc.y += xv.y*u_.y; sxc.z += xv.z*u_.y; sxc.w += xv.w*u_.y;
        half2 h01 = __floats2half2_rn(xv.x, xv.y);
        half2 h23 = __floats2half2_rn(xv.z, xv.w);
        uint2 pk;
        pk.x = *reinterpret_cast<unsigned int*>(&h01);
        pk.y = *reinterpret_cast<unsigned int*>(&h23);
        xs[d * 32 + lane] = pk;
    }

    // stats to smem: float4 layout [(w*32+lane)*4 + stat]
    {
        float4* red4 = (float4*)red;
        int base = (w * 32 + lane) * 4;
        red4[base + 0] = dot;
        red4[base + 1] = s1;
        red4[base + 2] = s2;
        red4[base + 3] = sxc;
    }

    // Sc/Scc from uc (local, tiny)
    {
        float c0 = uc[tid].y, c1 = uc[tid + 256].y;
        float ls = c0 + c1, lss = c0 * c0 + c1 * c1;
        ls = warpSum(ls); lss = warpSum(lss);
        if (lane == 0) { r32[w] = ls; r32[8 + w] = lss; }
    }
    __syncthreads();

    // ---- Reduce per-t stats across the 8 warps. Thread tid<128 owns t_local=tid.
    float score = 0.f, v1 = 0.f, v2 = 0.f, vx = 0.f;
    if (tid < 128) {
        int lo = tid >> 2, i = tid & 3;
        float a0 = 0.f, a1 = 0.f, a2 = 0.f, a3 = 0.f;
        #pragma unroll
        for (int rg = 0; rg < 8; rg++) {
            int base = (rg * 32 + lo) * 16 + i;
            a0 += red[base];
            a1 += red[base + 4];
            a2 += red[base + 8];
            a3 += red[base + 12];
        }
        score = a0 * 0.17677669529663687f;   // 1/sqrt(32)
        v1 = a1; v2 = a2; vx = a3;
        float m = warpMax(score);
        if (lane == 0) r32[16 + w] = m;
    }
    __syncthreads();
    if (tid == 0) {
        sSc[0] = r32[0]+r32[1]+r32[2]+r32[3]+r32[4]+r32[5]+r32[6]+r32[7];
        sSc[1] = r32[8]+r32[9]+r32[10]+r32[11]+r32[12]+r32[13]+r32[14]+r32[15];
        float m = fmaxf(fmaxf(r32[16], r32[17]), fmaxf(r32[18], r32[19]));
        unsigned int la = smem_u32 + MAXOFF + rank * 4;
        #pragma unroll
        for (int dst = 0; dst < CH; dst++) stc_f1(la, dst, m);
    }
    CLUSTER_SYNC();

    float M = -1e30f;
    #pragma unroll
    for (int i = 0; i < CH; i++) M = fmaxf(M, maxb[i]);
    float e = 0.f;
    if (tid < 128) {
        e = expf(score - M);
        float se = warpSum(e);
        if (lane == 0) r32[20 + w] = se;
    }
    __syncthreads();
    if (tid == 0) {
        float s = r32[20] + r32[21] + r32[22] + r32[23];
        unsigned int la = smem_u32 + DENOFF + rank * 4;
        #pragma unroll
        for (int dst = 0; dst < CH; dst++) stc_f1(la, dst, s);
    }
    CLUSTER_SYNC();

    float denom = denb[0]+denb[1]+denb[2]+denb[3]+denb[4]+denb[5]+denb[6]+denb[7];
    if (tid < 128) {
        float wgt = e / denom;
        float mu = (v1 + wgt * sSc[0]) * (1.f / DD);
        float ms = (v2 + 2.f * wgt * vx + wgt * wgt * sSc[1]) * (1.f / DD);
        float rs = rsqrtf(ms - mu * mu + 1e-5f);
        rstd_s[tid] = rs;                     // LOCAL only — no broadcast
        float r1 = warpSum(rs * wgt);
        float r2 = warpSum(rs * mu);
        if (lane == 0) { r32[24 + w] = r1; r32[28 + w] = r2; }
    }
    __syncthreads();
    if (tid == 0) {
        g_R1p[b * CH + rank] = r32[24] + r32[25] + r32[26] + r32[27];
        g_R2p[b * CH + rank] = r32[28] + r32[29] + r32[30] + r32[31];
    }
    // rstd_s visible after the __syncthreads above; no more cluster traffic.

    // ---- Phase 2: A_partial[d] = sum over LOCAL 128 t of rstd[t]*x[d,t].
    // Warp w owns d in [w*64, w*64+64). rstd float4 per lane loaded once.
    float4 rv = *(const float4*)(rstd_s + 4 * lane);
    float* apb = g_Ap + ((size_t)rank * BB + b) * DD;
    #pragma unroll 4
    for (int j = 0; j < 64; j++) {
        int d = w * 64 + j;
        uint2 pk = xs[d * 32 + lane];
        half2 h01 = *reinterpret_cast<half2*>(&pk.x);
        half2 h23 = *reinterpret_cast<half2*>(&pk.y);
        float2 f01 = __half22float2(h01);
        float2 f23 = __half22float2(h23);
        float acc = f01.x * rv.x + f01.y * rv.y + f23.x * rv.z + f23.y * rv.w;
        acc = warpSum(acc);
        if (lane == 0) apb[d] = acc;
    }
}

// ---------------------------------------------------------------------------
// Kernel 5: pooled + MLP head + output (A summed from rank partials).
// ---------------------------------------------------------------------------
__global__ void k5_head(const float* __restrict__ ln1g, const float* __restrict__ ln1b,
                        const float* __restrict__ W1, const float* __restrict__ b1,
                        const float* __restrict__ ln2g, const float* __restrict__ ln2b,
                        const float* __restrict__ W2, const float* __restrict__ b2,
                        float* __restrict__ out) {
    int b = blockIdx.x, tid = threadIdx.x;
    int w = tid >> 5, lane = tid & 31;
    __shared__ float pooled[DD];
    __shared__ float t1[HH];
    __shared__ float act[HH];
    __shared__ float smu, srstd;

    float R1 = 0.f, R2 = 0.f;
    #pragma unroll
    for (int i = 0; i < CH; i++) { R1 += g_R1p[b * CH + i]; R2 += g_R2p[b * CH + i]; }

    #pragma unroll
    for (int it = 0; it < 2; it++) {
        int d = tid + it * 256;
        float Ad = 0.f;
        #pragma unroll
        for (int r = 0; r < CH; r++) Ad += g_Ap[((size_t)r * BB + b) * DD + d];
        pooled[d] = ln1g[d] * ((Ad + g_c[b * DD + d] * R1 - R2) * (1.f / TT)) + ln1b[d];
    }
    __syncthreads();

    #pragma unroll
    for (int hh = 0; hh < 8; hh++) {
        int h = w * 8 + hh;
        float acc = 0.f;
        #pragma unroll
        for (int i = 0; i < 16; i++) {
            int d = lane + 32 * i;
            acc += pooled[d] * W1[h * DD + d];
        }
        acc = warpSum(acc);
        if (lane == 0) t1[h] = acc + b1[h];
    }
    __syncthreads();

    if (w == 0) {
        float a = t1[lane], bb = t1[lane + 32];
        float sum = warpSum(a + bb) * (1.f / HH);
        float sq  = warpSum(a * a + bb * bb) * (1.f / HH);
        if (lane == 0) { smu = sum; srstd = rsqrtf(sq - sum * sum + 1e-5f); }
    }
    __syncthreads();

    if (tid < HH) {
        float v = (t1[tid] - smu) * srstd * ln2g[tid] + ln2b[tid];
        act[tid] = v > 0.f ? v : (expf(v) - 1.f);  // ELU
    }
    __syncthreads();

    if (w < CC) {
        float acc = act[lane] * W2[w * HH + lane] + act[lane + 32] * W2[w * HH + lane + 32];
        acc = warpSum(acc);
        if (lane == 0) out[b * CC + w] = acc + b2[w];
    }
}

extern "C" void kernel_launch(void* const* d_in, const int* in_sizes, int n_in,
                              void* d_out, int out_size) {
    const float* tcf  = (const float*)d_in[0];
    const float* gaf  = (const float*)d_in[1];
    const float* Wq   = (const float*)d_in[2];
    const float* Wkv  = (const float*)d_in[3];
    const float* Wout = (const float*)d_in[4];
    const float* ln1g = (const float*)d_in[5];
    const float* ln1b = (const float*)d_in[6];
    const float* W1   = (const float*)d_in[7];
    const float* b1   = (const float*)d_in[8];
    const float* ln2g = (const float*)d_in[9];
    const float* ln2b = (const float*)d_in[10];
    const float* W2   = (const float*)d_in[11];
    const float* b2   = (const float*)d_in[12];
    float* out = (float*)d_out;

    cudaFuncSetAttribute(k_main, cudaFuncAttributeMaxDynamicSharedMemorySize, SMEM_MAIN);

    k1_prep<<<dim3(4, BB), 128>>>(gaf, Wq, Wkv, Wout);
    k_main<<<dim3(CH, BB), 256, SMEM_MAIN>>>(tcf);
    k5_head<<<BB, 256>>>(ln1g, ln1b, W1, b1, ln2g, ln2b, W2, b2, out);
}

// round 12
// speedup vs baseline: 1.0518x; 1.0518x over previous
#include <cuda_runtime.h>
#include <cstdint>
#include <math.h>

#define BB 128
#define DD 512
#define TT 1024
#define GG 256
#define KK 32
#define HH 64
#define CC 4
#define CH 8          // CTAs per cluster == d-chunks per batch
#define DCH 64        // d rows per CTA

// Scratch (allocation-free rule: __device__ globals)
__device__ float g_c[BB*DD];
__device__ float g_R1p[BB*CH];
__device__ float g_R2p[BB*CH];
__device__ float g_A[BB*DD];

// dynamic smem layout (bytes). Padded to 72 KB to force exactly 3 CTAs/SM
// (3*72 = 216 KB <= 228; 4*72 = 288 > 228) so in-flight x-data (444 CTAs *
// 256 KB = 111 MB) fits in L2 and pass-2 re-reads hit L2.
#define INBOXOFF 0            // float4 inbox[8][128]   = 16384
#define RSTDOFF  16384        // float rstd[1024]       = 4096
#define CSOFF    20480        // float c[512]           = 2048
#define USOFF    22528        // float u[64]            = 256
#define GAFOFF   22784        // float gaf[256]         = 1024
#define KVOFF    23808        // float kv[32]           = 128
#define MAXOFF   23936        // float maxb[8]          = 32
#define DENOFF   23968        // float denb[8]          = 32
#define REDOFF   24000        // float red[32]          = 128
#define SCOFF    24128        // float sSc[2]           = 8
#define SMEM_MAIN 73728       // 72 KB (padded)

__device__ __forceinline__ float warpSum(float v) {
    #pragma unroll
    for (int o = 16; o > 0; o >>= 1) v += __shfl_xor_sync(0xffffffffu, v, o);
    return v;
}
__device__ __forceinline__ float warpMax(float v) {
    #pragma unroll
    for (int o = 16; o > 0; o >>= 1) v = fmaxf(v, __shfl_xor_sync(0xffffffffu, v, o));
    return v;
}
__device__ __forceinline__ void stc_f4(unsigned int laddr, int rank, float4 v) {
    unsigned int ra;
    asm volatile("mapa.shared::cluster.u32 %0, %1, %2;" : "=r"(ra) : "r"(laddr), "r"(rank));
    asm volatile("st.shared::cluster.v4.f32 [%0], {%1,%2,%3,%4};"
                 :: "r"(ra), "f"(v.x), "f"(v.y), "f"(v.z), "f"(v.w) : "memory");
}
__device__ __forceinline__ void stc_f1(unsigned int laddr, int rank, float v) {
    unsigned int ra;
    asm volatile("mapa.shared::cluster.u32 %0, %1, %2;" : "=r"(ra) : "r"(laddr), "r"(rank));
    asm volatile("st.shared::cluster.f32 [%0], %1;" :: "r"(ra), "f"(v) : "memory");
}
#define CLUSTER_SYNC() do { \
    asm volatile("barrier.cluster.arrive.aligned;" ::: "memory"); \
    asm volatile("barrier.cluster.wait.aligned;" ::: "memory"); \
} while (0)

// ---------------------------------------------------------------------------
// Fused main kernel: cluster of 8 CTAs per batch; NO smem stash. Pass-1
// streams from DRAM (populating L2); pass-2 re-reads the same 256 KB slice
// from L2. 3 CTAs/SM so every tail overlaps other clusters' streaming.
// k1 is merged into the prologue (redundant per-CTA KV/c/u compute).
// ---------------------------------------------------------------------------
__global__ void __launch_bounds__(256, 3) __cluster_dims__(CH, 1, 1)
k_main(const float* __restrict__ tcf, const float* __restrict__ gaf,
       const float* __restrict__ Wq, const float* __restrict__ Wkv,
       const float* __restrict__ Wout) {
    extern __shared__ char smem[];
    float4* inbox  = (float4*)(smem + INBOXOFF);
    float*  rstd_s = (float*)(smem + RSTDOFF);
    float*  c_s    = (float*)(smem + CSOFF);
    float*  u_s    = (float*)(smem + USOFF);
    float*  s_gaf  = (float*)(smem + GAFOFF);
    float*  s_kv   = (float*)(smem + KVOFF);
    float*  maxb   = (float*)(smem + MAXOFF);
    float*  denb   = (float*)(smem + DENOFF);
    float*  red    = (float*)(smem + REDOFF);
    float*  sSc    = (float*)(smem + SCOFF);

    const int rank = blockIdx.x;      // d-chunk index within batch
    const int b    = blockIdx.y;
    const int tid  = threadIdx.x;
    const int lane = tid & 31, w = tid >> 5;

    unsigned int smem_u32 = (unsigned int)__cvta_generic_to_shared(smem);

    // ================= Prologue (merged k1): KV, c (all 512), u (own 64) ====
    s_gaf[tid] = gaf[b * GG + tid];
    __syncthreads();

    // warp w computes k = 4w..4w+3, lanes sweep g coalesced
    #pragma unroll
    for (int kk = 0; kk < 4; kk++) {
        int k = w * 4 + kk;
        float acc = 0.f;
        #pragma unroll
        for (int i = 0; i < 8; i++) {
            int g = lane + 32 * i;
            acc += s_gaf[g] * Wkv[k * GG + g];
        }
        acc = warpSum(acc);
        if (lane == 0) s_kv[k] = acc;
    }
    __syncthreads();

    // c for all 512 d (needed for Sc/Scc); u for own 64 d.
    float lsc = 0.f, lscc = 0.f;
    #pragma unroll
    for (int it = 0; it < 2; it++) {
        int d = tid + it * 256;
        float cc = 0.f;
        const float4* wo = (const float4*)(Wout + d * KK);
        #pragma unroll
        for (int q = 0; q < 8; q++) {
            float4 v = wo[q];
            cc += v.x * s_kv[q*4] + v.y * s_kv[q*4+1] + v.z * s_kv[q*4+2] + v.w * s_kv[q*4+3];
        }
        c_s[d] = cc;
        lsc += cc; lscc += cc * cc;
    }
    lsc = warpSum(lsc); lscc = warpSum(lscc);
    if (lane == 0) { red[w] = lsc; red[8 + w] = lscc; }
    if (tid < DCH) {
        int d = rank * DCH + tid;
        float uu = 0.f;
        #pragma unroll
        for (int k = 0; k < KK; k++) uu += Wq[k * DD + d] * s_kv[k];
        u_s[tid] = uu;
    }
    __syncthreads();
    if (tid == 0) {
        float a = 0.f, bb2 = 0.f;
        #pragma unroll
        for (int i = 0; i < 8; i++) { a += red[i]; bb2 += red[8 + i]; }
        sSc[0] = a; sSc[1] = bb2;
    }
    // export own 64 c's for k5
    if (tid < DCH) g_c[b * DD + rank * DCH + tid] = c_s[rank * DCH + tid];
    __syncthreads();

    // ================= Pass 1: stream own 64 rows x 1024 t (DRAM -> L2) =====
    const float4* xp = (const float4*)(tcf + ((size_t)b * DD + (size_t)rank * DCH) * TT) + tid;
    float4 dot = {0,0,0,0}, s1 = {0,0,0,0}, s2 = {0,0,0,0}, sxc = {0,0,0,0};

    #pragma unroll 16
    for (int r = 0; r < DCH; r++) {
        float4 xv = xp[r * (TT/4)];
        float uu = u_s[r];
        float cc = c_s[rank * DCH + r];
        dot.x += xv.x*uu; dot.y += xv.y*uu; dot.z += xv.z*uu; dot.w += xv.w*uu;
        s1.x  += xv.x;    s1.y  += xv.y;    s1.z  += xv.z;    s1.w  += xv.w;
        s2.x  += xv.x*xv.x; s2.y += xv.y*xv.y; s2.z += xv.z*xv.z; s2.w += xv.w*xv.w;
        sxc.x += xv.x*cc; sxc.y += xv.y*cc; sxc.z += xv.z*cc; sxc.w += xv.w*cc;
    }

    // ---- Send per-t stat partials to owner CTA (dest rank = warp id).
    {
        unsigned int addr = smem_u32 + INBOXOFF + (unsigned int)(rank * 128 + lane * 4) * 16;
        int dst = w;
        stc_f4(addr,      dst, make_float4(dot.x, s1.x, s2.x, sxc.x));
        stc_f4(addr + 16, dst, make_float4(dot.y, s1.y, s2.y, sxc.y));
        stc_f4(addr + 32, dst, make_float4(dot.z, s1.z, s2.z, sxc.z));
        stc_f4(addr + 48, dst, make_float4(dot.w, s1.w, s2.w, sxc.w));
    }
    CLUSTER_SYNC();

    // ---- Reduce stats for own 128 t's (threads 0..127: t_local = tid)
    float score = 0.f, v1 = 0.f, v2 = 0.f, vx = 0.f;
    if (tid < 128) {
        float4 acc = {0,0,0,0};
        #pragma unroll
        for (int s = 0; s < CH; s++) {
            float4 v = inbox[s * 128 + tid];
            acc.x += v.x; acc.y += v.y; acc.z += v.z; acc.w += v.w;
        }
        score = acc.x * 0.17677669529663687f;   // 1/sqrt(32)
        v1 = acc.y; v2 = acc.z; vx = acc.w;
        float m = warpMax(score);
        if (lane == 0) red[16 + w] = m;
    }
    __syncthreads();
    if (tid == 0) {
        float m = fmaxf(fmaxf(red[16], red[17]), fmaxf(red[18], red[19]));
        unsigned int la = smem_u32 + MAXOFF + rank * 4;
        #pragma unroll
        for (int dst = 0; dst < CH; dst++) stc_f1(la, dst, m);
    }
    CLUSTER_SYNC();

    float M = fmaxf(fmaxf(fmaxf(maxb[0], maxb[1]), fmaxf(maxb[2], maxb[3])),
                    fmaxf(fmaxf(maxb[4], maxb[5]), fmaxf(maxb[6], maxb[7])));
    float e = 0.f;
    if (tid < 128) {
        e = expf(score - M);
        float se = warpSum(e);
        if (lane == 0) red[20 + w] = se;
    }
    __syncthreads();
    if (tid == 0) {
        float s = red[20] + red[21] + red[22] + red[23];
        unsigned int la = smem_u32 + DENOFF + rank * 4;
        #pragma unroll
        for (int dst = 0; dst < CH; dst++) stc_f1(la, dst, s);
    }
    CLUSTER_SYNC();

    float denom = denb[0]+denb[1]+denb[2]+denb[3]+denb[4]+denb[5]+denb[6]+denb[7];
    if (tid < 128) {
        float wgt = e / denom;
        float mu = (v1 + wgt * sSc[0]) * (1.f / DD);
        float ms = (v2 + 2.f * wgt * vx + wgt * wgt * sSc[1]) * (1.f / DD);
        float rs = rsqrtf(ms - mu * mu + 1e-5f);
        int tg = rank * 128 + tid;
        unsigned int la = smem_u32 + RSTDOFF + (unsigned int)tg * 4;
        #pragma unroll
        for (int dst = 0; dst < CH; dst++) stc_f1(la, dst, rs);
        float r1 = warpSum(rs * wgt);
        float r2 = warpSum(rs * mu);
        if (lane == 0) { red[24 + w] = r1; red[28 + w] = r2; }
    }
    __syncthreads();
    if (tid == 0) {
        g_R1p[b * CH + rank] = red[24] + red[25] + red[26] + red[27];
        g_R2p[b * CH + rank] = red[28] + red[29] + red[30] + red[31];
    }
    CLUSTER_SYNC();   // all rstd values delivered everywhere

    // ================= Pass 2: A[d] = sum_t rstd[t]*x[d,t]; x from L2 =======
    // Warp w owns rows w*8 .. w*8+7.
    #pragma unroll
    for (int rr = 0; rr < 8; rr++) {
        int row = w * 8 + rr;
        int d = rank * DCH + row;
        const float4* xr = (const float4*)(tcf + ((size_t)b * DD + d) * TT);
        float acc = 0.f;
        #pragma unroll
        for (int j = 0; j < 8; j++) {
            float4 xv = xr[lane + j * 32];
            float4 rv = *(const float4*)(rstd_s + (lane + j * 32) * 4);
            acc += xv.x*rv.x + xv.y*rv.y + xv.z*rv.z + xv.w*rv.w;
        }
        acc = warpSum(acc);
        if (lane == 0) g_A[b * DD + d] = acc;
    }
}

// ---------------------------------------------------------------------------
// Kernel 5: pooled + MLP head + output — warp-parallel.
// ---------------------------------------------------------------------------
__global__ void k5_head(const float* __restrict__ ln1g, const float* __restrict__ ln1b,
                        const float* __restrict__ W1, const float* __restrict__ b1,
                        const float* __restrict__ ln2g, const float* __restrict__ ln2b,
                        const float* __restrict__ W2, const float* __restrict__ b2,
                        float* __restrict__ out) {
    int b = blockIdx.x, tid = threadIdx.x;
    int w = tid >> 5, lane = tid & 31;
    __shared__ float pooled[DD];
    __shared__ float t1[HH];
    __shared__ float act[HH];
    __shared__ float smu, srstd;

    float R1 = 0.f, R2 = 0.f;
    #pragma unroll
    for (int i = 0; i < CH; i++) { R1 += g_R1p[b * CH + i]; R2 += g_R2p[b * CH + i]; }

    #pragma unroll
    for (int it = 0; it < 2; it++) {
        int d = tid + it * 256;
        pooled[d] = ln1g[d] * ((g_A[b * DD + d] + g_c[b * DD + d] * R1 - R2) * (1.f / TT)) + ln1b[d];
    }
    __syncthreads();

    #pragma unroll
    for (int hh = 0; hh < 8; hh++) {
        int h = w * 8 + hh;
        float acc = 0.f;
        #pragma unroll
        for (int i = 0; i < 16; i++) {
            int d = lane + 32 * i;
            acc += pooled[d] * W1[h * DD + d];
        }
        acc = warpSum(acc);
        if (lane == 0) t1[h] = acc + b1[h];
    }
    __syncthreads();

    if (w == 0) {
        float a = t1[lane], bb = t1[lane + 32];
        float sum = warpSum(a + bb) * (1.f / HH);
        float sq  = warpSum(a * a + bb * bb) * (1.f / HH);
        if (lane == 0) { smu = sum; srstd = rsqrtf(sq - sum * sum + 1e-5f); }
    }
    __syncthreads();

    if (tid < HH) {
        float v = (t1[tid] - smu) * srstd * ln2g[tid] + ln2b[tid];
        act[tid] = v > 0.f ? v : (expf(v) - 1.f);  // ELU
    }
    __syncthreads();

    if (w < CC) {
        float acc = act[lane] * W2[w * HH + lane] + act[lane + 32] * W2[w * HH + lane + 32];
        acc = warpSum(acc);
        if (lane == 0) out[b * CC + w] = acc + b2[w];
    }
}

extern "C" void kernel_launch(void* const* d_in, const int* in_sizes, int n_in,
                              void* d_out, int out_size) {
    const float* tcf  = (const float*)d_in[0];
    const float* gaf  = (const float*)d_in[1];
    const float* Wq   = (const float*)d_in[2];
    const float* Wkv  = (const float*)d_in[3];
    const float* Wout = (const float*)d_in[4];
    const float* ln1g = (const float*)d_in[5];
    const float* ln1b = (const float*)d_in[6];
    const float* W1   = (const float*)d_in[7];
    const float* b1   = (const float*)d_in[8];
    const float* ln2g = (const float*)d_in[9];
    const float* ln2b = (const float*)d_in[10];
    const float* W2   = (const float*)d_in[11];
    const float* b2   = (const float*)d_in[12];
    float* out = (float*)d_out;

    cudaFuncSetAttribute(k_main, cudaFuncAttributeMaxDynamicSharedMemorySize, SMEM_MAIN);

    k_main<<<dim3(CH, BB), 256, SMEM_MAIN>>>(tcf, gaf, Wq, Wkv, Wout);
    k5_head<<<BB, 256>>>(ln1g, ln1b, W1, b1, ln2g, ln2b, W2, b2, out);
}

// round 13
// speedup vs baseline: 1.0931x; 1.0393x over previous
#include <cuda_runtime.h>
#include <cstdint>
#include <math.h>

#define BB 128
#define DD 512
#define TT 1024
#define GG 256
#define KK 32
#define HH 64
#define CC 4
#define QB 32          // batches per quarter (64 MB working set -> L2 resident)
#define SCALE 0.17677669529663687f   // 1/sqrt(32)

// Scratch (allocation-free rule: __device__ globals)
__device__ float g_kv[BB*KK];
__device__ float g_u[BB*DD];
__device__ float g_c[BB*DD];
__device__ float g_Sc[BB];
__device__ float g_Scc[BB];
__device__ float g_sc[BB*TT];
__device__ float g_s1[BB*TT];
__device__ float g_s2[BB*TT];
__device__ float g_sx[BB*TT];
__device__ float g_rstd[BB*TT];
__device__ float g_R1[BB];
__device__ float g_R2[BB];
__device__ float g_A[BB*DD];

__device__ __forceinline__ float warpSum(float v) {
    #pragma unroll
    for (int o = 16; o > 0; o >>= 1) v += __shfl_xor_sync(0xffffffffu, v, o);
    return v;
}
__device__ __forceinline__ float warpMax(float v) {
    #pragma unroll
    for (int o = 16; o > 0; o >>= 1) v = fmaxf(v, __shfl_xor_sync(0xffffffffu, v, o));
    return v;
}

// ---------------------------------------------------------------------------
// k1a: KV[b,k] = sum_g gaf[b,g] * Wkv[k,g].  One block per b.
// ---------------------------------------------------------------------------
__global__ void __launch_bounds__(256) k1a_kv(const float* __restrict__ gaf,
                                              const float* __restrict__ Wkv) {
    int b = blockIdx.x, tid = threadIdx.x, w = tid >> 5, lane = tid & 31;
    __shared__ float s_gaf[GG];
    s_gaf[tid] = gaf[b * GG + tid];
    __syncthreads();
    #pragma unroll
    for (int kk = 0; kk < 4; kk++) {
        int k = w * 4 + kk;
        float acc = 0.f;
        #pragma unroll
        for (int i = 0; i < 8; i++)
            acc += s_gaf[lane + 32 * i] * Wkv[k * GG + lane + 32 * i];
        acc = warpSum(acc);
        if (lane == 0) g_kv[b * KK + k] = acc;
    }
}

// ---------------------------------------------------------------------------
// k1b: u[b,d], c[b,d], Sc[b], Scc[b].  One block (512 threads) per b.
// ---------------------------------------------------------------------------
__global__ void __launch_bounds__(512) k1b_uc(const float* __restrict__ Wq,
                                              const float* __restrict__ Wout) {
    int b = blockIdx.x, tid = threadIdx.x, w = tid >> 5, lane = tid & 31;
    __shared__ float s_kv[KK];
    __shared__ float red[32];
    if (tid < KK) s_kv[tid] = g_kv[b * KK + tid];
    __syncthreads();

    int d = tid;
    float uu = 0.f;
    #pragma unroll
    for (int k = 0; k < KK; k++) uu += Wq[k * DD + d] * s_kv[k];   // coalesced
    float cc = 0.f;
    const float4* wo = (const float4*)(Wout + d * KK);
    #pragma unroll
    for (int qq = 0; qq < 8; qq++) {
        float4 v = wo[qq];
        cc += v.x*s_kv[qq*4] + v.y*s_kv[qq*4+1] + v.z*s_kv[qq*4+2] + v.w*s_kv[qq*4+3];
    }
    g_u[b * DD + d] = uu;
    g_c[b * DD + d] = cc;

    float ls = warpSum(cc), lss = warpSum(cc * cc);
    if (lane == 0) { red[w] = ls; red[16 + w] = lss; }
    __syncthreads();
    if (tid == 0) {
        float a = 0.f, s = 0.f;
        #pragma unroll
        for (int i = 0; i < 16; i++) { a += red[i]; s += red[16 + i]; }
        g_Sc[b] = a; g_Scc[b] = s;
    }
}

// ---------------------------------------------------------------------------
// k2(q): stats pass. Block = (t-slice ts, batch). Covers 128 t x all 512 d.
// Thread (dg=tid/32, lane): rows d = dg*64..+64, t = ts*128 + 4*lane..+4.
// Writes FINAL per-t scores/S1/S2/Sxc (reduced over d in-block).
// ---------------------------------------------------------------------------
__global__ void __launch_bounds__(256) k2_stats(const float* __restrict__ tcf, int q) {
    int ts = blockIdx.x, b = q * QB + blockIdx.y;
    int tid = threadIdx.x, dg = tid >> 5, lane = tid & 31;
    __shared__ float s_u[DD], s_c[DD];
    __shared__ float red[8 * 32 * 16];   // 16 KB: 8 dgroups x 32 lanes x 4 stats x float4

    #pragma unroll
    for (int it = 0; it < 2; it++) {
        int d = tid + it * 256;
        s_u[d] = g_u[b * DD + d];
        s_c[d] = g_c[b * DD + d];
    }
    __syncthreads();

    const float4* xp = (const float4*)(tcf + ((size_t)b * DD + dg * 64) * TT + ts * 128) + lane;
    float4 dot = {0,0,0,0}, s1 = {0,0,0,0}, s2 = {0,0,0,0}, sx = {0,0,0,0};

    #pragma unroll 16
    for (int r = 0; r < 64; r++) {
        float4 xv = xp[(size_t)r * 256];       // row stride = 1024 floats
        float uu = s_u[dg * 64 + r];
        float cc = s_c[dg * 64 + r];
        dot.x += xv.x*uu; dot.y += xv.y*uu; dot.z += xv.z*uu; dot.w += xv.w*uu;
        s1.x  += xv.x;    s1.y  += xv.y;    s1.z  += xv.z;    s1.w  += xv.w;
        s2.x  += xv.x*xv.x; s2.y += xv.y*xv.y; s2.z += xv.z*xv.z; s2.w += xv.w*xv.w;
        sx.x  += xv.x*cc; sx.y  += xv.y*cc; sx.z  += xv.z*cc; sx.w  += xv.w*cc;
    }

    float4* red4 = (float4*)red;
    int base = (dg * 32 + lane) * 4;
    red4[base + 0] = dot;
    red4[base + 1] = s1;
    red4[base + 2] = s2;
    red4[base + 3] = sx;
    __syncthreads();

    if (tid < 128) {                      // t_local = tid
        int lo = tid >> 2, comp = tid & 3;
        float a0 = 0.f, a1 = 0.f, a2 = 0.f, a3 = 0.f;
        #pragma unroll
        for (int g2 = 0; g2 < 8; g2++) {
            int bx = ((g2 * 32 + lo) * 4) * 4 + comp;
            a0 += red[bx];
            a1 += red[bx + 4];
            a2 += red[bx + 8];
            a3 += red[bx + 12];
        }
        int idx = b * TT + ts * 128 + tid;
        g_sc[idx] = a0 * SCALE;
        g_s1[idx] = a1;
        g_s2[idx] = a2;
        g_sx[idx] = a3;
    }
}

// ---------------------------------------------------------------------------
// k3(q): per-batch softmax over T, rstd[t], R1, R2.  One block per b.
// ---------------------------------------------------------------------------
__global__ void __launch_bounds__(256) k3_softmax(int q) {
    int b = q * QB + blockIdx.x;
    int tid = threadIdx.x, w = tid >> 5, lane = tid & 31;
    __shared__ float red[8], redb[8];
    __shared__ float bval;

    float4 sc4 = *(const float4*)(g_sc + b * TT + tid * 4);
    float m = fmaxf(fmaxf(sc4.x, sc4.y), fmaxf(sc4.z, sc4.w));
    m = warpMax(m);
    if (lane == 0) red[w] = m;
    __syncthreads();
    if (tid == 0) {
        float mm = red[0];
        for (int i = 1; i < 8; i++) mm = fmaxf(mm, red[i]);
        bval = mm;
    }
    __syncthreads();
    m = bval;

    float ee[4];
    ee[0] = expf(sc4.x - m); ee[1] = expf(sc4.y - m);
    ee[2] = expf(sc4.z - m); ee[3] = expf(sc4.w - m);
    float se = warpSum(ee[0] + ee[1] + ee[2] + ee[3]);
    __syncthreads();
    if (lane == 0) red[w] = se;
    __syncthreads();
    if (tid == 0) {
        float s = 0.f;
        for (int i = 0; i < 8; i++) s += red[i];
        bval = s;
    }
    __syncthreads();
    float inv = 1.f / bval;

    float Scb = g_Sc[b], Sccb = g_Scc[b];
    float4 v1 = *(const float4*)(g_s1 + b * TT + tid * 4);
    float4 v2 = *(const float4*)(g_s2 + b * TT + tid * 4);
    float4 vx = *(const float4*)(g_sx + b * TT + tid * 4);
    float vs1[4] = {v1.x, v1.y, v1.z, v1.w};
    float vs2[4] = {v2.x, v2.y, v2.z, v2.w};
    float vsx[4] = {vx.x, vx.y, vx.z, vx.w};

    float r1 = 0.f, r2 = 0.f, rs[4];
    #pragma unroll
    for (int i = 0; i < 4; i++) {
        float wgt = ee[i] * inv;
        float mu = (vs1[i] + wgt * Scb) * (1.f / DD);
        float ms = (vs2[i] + 2.f * wgt * vsx[i] + wgt * wgt * Sccb) * (1.f / DD);
        rs[i] = rsqrtf(ms - mu * mu + 1e-5f);
        r1 += rs[i] * wgt;
        r2 += rs[i] * mu;
    }
    *(float4*)(g_rstd + b * TT + tid * 4) = make_float4(rs[0], rs[1], rs[2], rs[3]);

    r1 = warpSum(r1); r2 = warpSum(r2);
    __syncthreads();
    if (lane == 0) { red[w] = r1; redb[w] = r2; }
    __syncthreads();
    if (tid == 0) {
        float a = 0.f, c = 0.f;
        for (int i = 0; i < 8; i++) { a += red[i]; c += redb[i]; }
        g_R1[b] = a; g_R2[b] = c;
    }
}

// ---------------------------------------------------------------------------
// k4(q): A[b,d] = sum_t rstd[b,t]*x[b,d,t]. Re-reads quarter's tcf from L2.
// Block = (chunk ch, batch): 64 d rows; rstd staged once in smem.
// ---------------------------------------------------------------------------
__global__ void __launch_bounds__(256) k4_A(const float* __restrict__ tcf, int q) {
    int ch = blockIdx.x, b = q * QB + blockIdx.y;
    int tid = threadIdx.x, w = tid >> 5, lane = tid & 31;
    __shared__ float4 s_r[TT/4];   // 4 KB

    s_r[tid] = ((const float4*)(g_rstd + b * TT))[tid];
    __syncthreads();

    #pragma unroll
    for (int rr = 0; rr < 8; rr++) {
        int d = ch * 64 + w * 8 + rr;
        const float4* xr = (const float4*)(tcf + ((size_t)b * DD + d) * TT);
        float acc = 0.f;
        #pragma unroll
        for (int j = 0; j < 8; j++) {
            float4 xv = xr[lane + j * 32];
            float4 rv = s_r[lane + j * 32];
            acc += xv.x*rv.x + xv.y*rv.y + xv.z*rv.z + xv.w*rv.w;
        }
        acc = warpSum(acc);
        if (lane == 0) g_A[b * DD + d] = acc;
    }
}

// ---------------------------------------------------------------------------
// k5: pooled + MLP head + output. ILP-heavy matvec (8 parallel h per warp).
// ---------------------------------------------------------------------------
__global__ void __launch_bounds__(256) k5_head(
        const float* __restrict__ ln1g, const float* __restrict__ ln1b,
        const float* __restrict__ W1, const float* __restrict__ b1,
        const float* __restrict__ ln2g, const float* __restrict__ ln2b,
        const float* __restrict__ W2, const float* __restrict__ b2,
        float* __restrict__ out) {
    int b = blockIdx.x, tid = threadIdx.x;
    int w = tid >> 5, lane = tid & 31;
    __shared__ float pooled[DD];
    __shared__ float t1[HH];
    __shared__ float act[HH];
    __shared__ float smu, srstd;

    float R1 = g_R1[b], R2 = g_R2[b];
    #pragma unroll
    for (int it = 0; it < 2; it++) {
        int d = tid + it * 256;
        pooled[d] = ln1g[d] * ((g_A[b * DD + d] + g_c[b * DD + d] * R1 - R2) * (1.f / TT)) + ln1b[d];
    }
    __syncthreads();

    // warp w -> h in [8w, 8w+8); 8 independent accumulators for MLP.
    float acc[8] = {0,0,0,0,0,0,0,0};
    #pragma unroll
    for (int i = 0; i < 16; i++) {
        float pd = pooled[lane + 32 * i];
        #pragma unroll
        for (int hh = 0; hh < 8; hh++)
            acc[hh] += pd * W1[(w * 8 + hh) * DD + lane + 32 * i];
    }
    #pragma unroll
    for (int hh = 0; hh < 8; hh++) {
        float a = warpSum(acc[hh]);
        if (lane == 0) t1[w * 8 + hh] = a + b1[w * 8 + hh];
    }
    __syncthreads();

    if (w == 0) {
        float a = t1[lane], bb = t1[lane + 32];
        float sum = warpSum(a + bb) * (1.f / HH);
        float sq  = warpSum(a * a + bb * bb) * (1.f / HH);
        if (lane == 0) { smu = sum; srstd = rsqrtf(sq - sum * sum + 1e-5f); }
    }
    __syncthreads();

    if (tid < HH) {
        float v = (t1[tid] - smu) * srstd * ln2g[tid] + ln2b[tid];
        act[tid] = v > 0.f ? v : (expf(v) - 1.f);  // ELU
    }
    __syncthreads();

    if (w < CC) {
        float acc2 = act[lane] * W2[w * HH + lane] + act[lane + 32] * W2[w * HH + lane + 32];
        acc2 = warpSum(acc2);
        if (lane == 0) out[b * CC + w] = acc2 + b2[w];
    }
}

extern "C" void kernel_launch(void* const* d_in, const int* in_sizes, int n_in,
                              void* d_out, int out_size) {
    const float* tcf  = (const float*)d_in[0];
    const float* gaf  = (const float*)d_in[1];
    const float* Wq   = (const float*)d_in[2];
    const float* Wkv  = (const float*)d_in[3];
    const float* Wout = (const float*)d_in[4];
    const float* ln1g = (const float*)d_in[5];
    const float* ln1b = (const float*)d_in[6];
    const float* W1   = (const float*)d_in[7];
    const float* b1   = (const float*)d_in[8];
    const float* ln2g = (const float*)d_in[9];
    const float* ln2b = (const float*)d_in[10];
    const float* W2   = (const float*)d_in[11];
    const float* b2   = (const float*)d_in[12];
    float* out = (float*)d_out;

    k1a_kv<<<BB, 256>>>(gaf, Wkv);
    k1b_uc<<<BB, 512>>>(Wq, Wout);
    for (int q = 0; q < 4; q++) {
        k2_stats<<<dim3(8, QB), 256>>>(tcf, q);
        k3_softmax<<<QB, 256>>>(q);
        k4_A<<<dim3(8, QB), 256>>>(tcf, q);
    }
    k5_head<<<BB, 256>>>(ln1g, ln1b, W1, b1, ln2g, ln2b, W2, b2, out);
}

// round 14
// speedup vs baseline: 1.2175x; 1.1138x over previous
#include <cuda_runtime.h>
#include <cstdint>
#include <math.h>

#define BB 128
#define DD 512
#define TT 1024
#define GG 256
#define KK 32
#define HH 64
#define CC 4
#define QB 32          // batches per quarter (64 MB working set -> L2 resident)
#define SCALE 0.17677669529663687f   // 1/sqrt(32)

// Scratch (allocation-free rule: __device__ globals)
__device__ float g_kv[BB*KK];
__device__ float g_u[BB*DD];
__device__ float g_c[BB*DD];
__device__ float g_Sc[BB];
__device__ float g_Scc[BB];
__device__ float g_sc[BB*TT];
__device__ float g_s1[BB*TT];
__device__ float g_s2[BB*TT];
__device__ float g_sx[BB*TT];
__device__ float g_R1[BB];
__device__ float g_R2[BB];
__device__ float g_A[BB*DD];

__device__ __forceinline__ float warpSum(float v) {
    #pragma unroll
    for (int o = 16; o > 0; o >>= 1) v += __shfl_xor_sync(0xffffffffu, v, o);
    return v;
}
__device__ __forceinline__ float warpMax(float v) {
    #pragma unroll
    for (int o = 16; o > 0; o >>= 1) v = fmaxf(v, __shfl_xor_sync(0xffffffffu, v, o));
    return v;
}

// ---------------------------------------------------------------------------
// k1a: KV[b,k] = sum_g gaf[b,g] * Wkv[k,g].  One block per b.
// ---------------------------------------------------------------------------
__global__ void __launch_bounds__(256) k1a_kv(const float* __restrict__ gaf,
                                              const float* __restrict__ Wkv) {
    int b = blockIdx.x, tid = threadIdx.x, w = tid >> 5, lane = tid & 31;
    __shared__ float s_gaf[GG];
    s_gaf[tid] = gaf[b * GG + tid];
    __syncthreads();
    #pragma unroll
    for (int kk = 0; kk < 4; kk++) {
        int k = w * 4 + kk;
        float acc = 0.f;
        #pragma unroll
        for (int i = 0; i < 8; i++)
            acc += s_gaf[lane + 32 * i] * Wkv[k * GG + lane + 32 * i];
        acc = warpSum(acc);
        if (lane == 0) g_kv[b * KK + k] = acc;
    }
}

// ---------------------------------------------------------------------------
// k1b: u[b,d], c[b,d], Sc[b], Scc[b].  One block (512 threads) per b.
// ---------------------------------------------------------------------------
__global__ void __launch_bounds__(512) k1b_uc(const float* __restrict__ Wq,
                                              const float* __restrict__ Wout) {
    int b = blockIdx.x, tid = threadIdx.x, w = tid >> 5, lane = tid & 31;
    __shared__ float s_kv[KK];
    __shared__ float red[32];
    if (tid < KK) s_kv[tid] = g_kv[b * KK + tid];
    __syncthreads();

    int d = tid;
    float uu = 0.f;
    #pragma unroll
    for (int k = 0; k < KK; k++) uu += Wq[k * DD + d] * s_kv[k];
    float cc = 0.f;
    const float4* wo = (const float4*)(Wout + d * KK);
    #pragma unroll
    for (int qq = 0; qq < 8; qq++) {
        float4 v = wo[qq];
        cc += v.x*s_kv[qq*4] + v.y*s_kv[qq*4+1] + v.z*s_kv[qq*4+2] + v.w*s_kv[qq*4+3];
    }
    g_u[b * DD + d] = uu;
    g_c[b * DD + d] = cc;

    float ls = warpSum(cc), lss = warpSum(cc * cc);
    if (lane == 0) { red[w] = ls; red[16 + w] = lss; }
    __syncthreads();
    if (tid == 0) {
        float a = 0.f, s = 0.f;
        #pragma unroll
        for (int i = 0; i < 16; i++) { a += red[i]; s += red[16 + i]; }
        g_Sc[b] = a; g_Scc[b] = s;
    }
}

// ---------------------------------------------------------------------------
// k2(q): stats pass. Block = (t-slice ts, batch). Covers 128 t x all 512 d.
// Writes FINAL per-t scores/S1/S2/Sxc (reduced over d in-block).
// ---------------------------------------------------------------------------
__global__ void __launch_bounds__(256) k2_stats(const float* __restrict__ tcf, int q) {
    int ts = blockIdx.x, b = q * QB + blockIdx.y;
    int tid = threadIdx.x, dg = tid >> 5, lane = tid & 31;
    __shared__ float s_u[DD], s_c[DD];
    __shared__ float red[8 * 32 * 16];   // 16 KB

    #pragma unroll
    for (int it = 0; it < 2; it++) {
        int d = tid + it * 256;
        s_u[d] = g_u[b * DD + d];
        s_c[d] = g_c[b * DD + d];
    }
    __syncthreads();

    const float4* xp = (const float4*)(tcf + ((size_t)b * DD + dg * 64) * TT + ts * 128) + lane;
    float4 dot = {0,0,0,0}, s1 = {0,0,0,0}, s2 = {0,0,0,0}, sx = {0,0,0,0};

    #pragma unroll 16
    for (int r = 0; r < 64; r++) {
        float4 xv = xp[(size_t)r * 256];
        float uu = s_u[dg * 64 + r];
        float cc = s_c[dg * 64 + r];
        dot.x += xv.x*uu; dot.y += xv.y*uu; dot.z += xv.z*uu; dot.w += xv.w*uu;
        s1.x  += xv.x;    s1.y  += xv.y;    s1.z  += xv.z;    s1.w  += xv.w;
        s2.x  += xv.x*xv.x; s2.y += xv.y*xv.y; s2.z += xv.z*xv.z; s2.w += xv.w*xv.w;
        sx.x  += xv.x*cc; sx.y  += xv.y*cc; sx.z  += xv.z*cc; sx.w  += xv.w*cc;
    }

    float4* red4 = (float4*)red;
    int base = (dg * 32 + lane) * 4;
    red4[base + 0] = dot;
    red4[base + 1] = s1;
    red4[base + 2] = s2;
    red4[base + 3] = sx;
    __syncthreads();

    if (tid < 128) {
        int lo = tid >> 2, comp = tid & 3;
        float a0 = 0.f, a1 = 0.f, a2 = 0.f, a3 = 0.f;
        #pragma unroll
        for (int g2 = 0; g2 < 8; g2++) {
            int bx = ((g2 * 32 + lo) * 4) * 4 + comp;
            a0 += red[bx];
            a1 += red[bx + 4];
            a2 += red[bx + 8];
            a3 += red[bx + 12];
        }
        int idx = b * TT + ts * 128 + tid;
        g_sc[idx] = a0 * SCALE;
        g_s1[idx] = a1;
        g_s2[idx] = a2;
        g_sx[idx] = a3;
    }
}

// ---------------------------------------------------------------------------
// k4(q): softmax+rstd prologue (redundant per block, L2-cheap), then
// A[b,d] = sum_t rstd[b,t]*x[b,d,t] with x re-read from L2.
// Block = (chunk ch, batch): 64 d rows.
// ---------------------------------------------------------------------------
__global__ void __launch_bounds__(256) k4_A(const float* __restrict__ tcf, int q) {
    int ch = blockIdx.x, b = q * QB + blockIdx.y;
    int tid = threadIdx.x, w = tid >> 5, lane = tid & 31;
    __shared__ float s_r[TT];      // rstd, 4 KB
    __shared__ float red[8], redb[8];
    __shared__ float bval;

    // ---- Prologue: per-batch softmax + rstd (identical in all 8 ch-blocks).
    float4 sc4 = ((const float4*)(g_sc + b * TT))[tid];
    float m = fmaxf(fmaxf(sc4.x, sc4.y), fmaxf(sc4.z, sc4.w));
    m = warpMax(m);
    if (lane == 0) red[w] = m;
    __syncthreads();
    if (tid == 0) {
        float mm = red[0];
        #pragma unroll
        for (int i = 1; i < 8; i++) mm = fmaxf(mm, red[i]);
        bval = mm;
    }
    __syncthreads();
    m = bval;

    float ee[4];
    ee[0] = expf(sc4.x - m); ee[1] = expf(sc4.y - m);
    ee[2] = expf(sc4.z - m); ee[3] = expf(sc4.w - m);
    float se = warpSum(ee[0] + ee[1] + ee[2] + ee[3]);
    __syncthreads();
    if (lane == 0) red[w] = se;
    __syncthreads();
    if (tid == 0) {
        float s = 0.f;
        #pragma unroll
        for (int i = 0; i < 8; i++) s += red[i];
        bval = s;
    }
    __syncthreads();
    float inv = 1.f / bval;

    float Scb = g_Sc[b], Sccb = g_Scc[b];
    float4 v1 = ((const float4*)(g_s1 + b * TT))[tid];
    float4 v2 = ((const float4*)(g_s2 + b * TT))[tid];
    float4 vx = ((const float4*)(g_sx + b * TT))[tid];
    float vs1[4] = {v1.x, v1.y, v1.z, v1.w};
    float vs2[4] = {v2.x, v2.y, v2.z, v2.w};
    float vsx[4] = {vx.x, vx.y, vx.z, vx.w};

    float r1 = 0.f, r2 = 0.f, rs[4];
    #pragma unroll
    for (int i = 0; i < 4; i++) {
        float wgt = ee[i] * inv;
        float mu = (vs1[i] + wgt * Scb) * (1.f / DD);
        float ms = (vs2[i] + 2.f * wgt * vsx[i] + wgt * wgt * Sccb) * (1.f / DD);
        rs[i] = rsqrtf(ms - mu * mu + 1e-5f);
        r1 += rs[i] * wgt;
        r2 += rs[i] * mu;
    }
    *(float4*)(s_r + tid * 4) = make_float4(rs[0], rs[1], rs[2], rs[3]);

    if (ch == 0) {
        r1 = warpSum(r1); r2 = warpSum(r2);
        if (lane == 0) { red[w] = r1; redb[w] = r2; }
        __syncthreads();
        if (tid == 0) {
            float a = 0.f, c = 0.f;
            #pragma unroll
            for (int i = 0; i < 8; i++) { a += red[i]; c += redb[i]; }
            g_R1[b] = a; g_R2[b] = c;
        }
    } else {
        __syncthreads();   // keep barrier counts aligned across branches? (all threads hit one)
    }
    __syncthreads();

    // ---- Main: A over own 64 d rows, x from L2.
    #pragma unroll
    for (int rr = 0; rr < 8; rr++) {
        int d = ch * 64 + w * 8 + rr;
        const float4* xr = (const float4*)(tcf + ((size_t)b * DD + d) * TT);
        float acc = 0.f;
        #pragma unroll
        for (int j = 0; j < 8; j++) {
            float4 xv = xr[lane + j * 32];
            float4 rv = *(const float4*)(s_r + (lane + j * 32) * 4);
            acc += xv.x*rv.x + xv.y*rv.y + xv.z*rv.z + xv.w*rv.w;
        }
        acc = warpSum(acc);
        if (lane == 0) g_A[b * DD + d] = acc;
    }
}

// ---------------------------------------------------------------------------
// k5: pooled + MLP head + output. ILP-heavy matvec.
// ---------------------------------------------------------------------------
__global__ void __launch_bounds__(256) k5_head(
        const float* __restrict__ ln1g, const float* __restrict__ ln1b,
        const float* __restrict__ W1, const float* __restrict__ b1,
        const float* __restrict__ ln2g, const float* __restrict__ ln2b,
        const float* __restrict__ W2, const float* __restrict__ b2,
        float* __restrict__ out) {
    int b = blockIdx.x, tid = threadIdx.x;
    int w = tid >> 5, lane = tid & 31;
    __shared__ float pooled[DD];
    __shared__ float t1[HH];
    __shared__ float act[HH];
    __shared__ float smu, srstd;

    float R1 = g_R1[b], R2 = g_R2[b];
    #pragma unroll
    for (int it = 0; it < 2; it++) {
        int d = tid + it * 256;
        pooled[d] = ln1g[d] * ((g_A[b * DD + d] + g_c[b * DD + d] * R1 - R2) * (1.f / TT)) + ln1b[d];
    }
    __syncthreads();

    float acc[8] = {0,0,0,0,0,0,0,0};
    #pragma unroll
    for (int i = 0; i < 16; i++) {
        float pd = pooled[lane + 32 * i];
        #pragma unroll
        for (int hh = 0; hh < 8; hh++)
            acc[hh] += pd * W1[(w * 8 + hh) * DD + lane + 32 * i];
    }
    #pragma unroll
    for (int hh = 0; hh < 8; hh++) {
        float a = warpSum(acc[hh]);
        if (lane == 0) t1[w * 8 + hh] = a + b1[w * 8 + hh];
    }
    __syncthreads();

    if (w == 0) {
        float a = t1[lane], bb = t1[lane + 32];
        float sum = warpSum(a + bb) * (1.f / HH);
        float sq  = warpSum(a * a + bb * bb) * (1.f / HH);
        if (lane == 0) { smu = sum; srstd = rsqrtf(sq - sum * sum + 1e-5f); }
    }
    __syncthreads();

    if (tid < HH) {
        float v = (t1[tid] - smu) * srstd * ln2g[tid] + ln2b[tid];
        act[tid] = v > 0.f ? v : (expf(v) - 1.f);
    }
    __syncthreads();

    if (w < CC) {
        float acc2 = act[lane] * W2[w * HH + lane] + act[lane + 32] * W2[w * HH + lane + 32];
        acc2 = warpSum(acc2);
        if (lane == 0) out[b * CC + w] = acc2 + b2[w];
    }
}

extern "C" void kernel_launch(void* const* d_in, const int* in_sizes, int n_in,
                              void* d_out, int out_size) {
    const float* tcf  = (const float*)d_in[0];
    const float* gaf  = (const float*)d_in[1];
    const float* Wq   = (const float*)d_in[2];
    const float* Wkv  = (const float*)d_in[3];
    const float* Wout = (const float*)d_in[4];
    const float* ln1g = (const float*)d_in[5];
    const float* ln1b = (const float*)d_in[6];
    const float* W1   = (const float*)d_in[7];
    const float* b1   = (const float*)d_in[8];
    const float* ln2g = (const float*)d_in[9];
    const float* ln2b = (const float*)d_in[10];
    const float* W2   = (const float*)d_in[11];
    const float* b2   = (const float*)d_in[12];
    float* out = (float*)d_out;

    k1a_kv<<<BB, 256>>>(gaf, Wkv);
    k1b_uc<<<BB, 512>>>(Wq, Wout);
    for (int q = 0; q < 4; q++) {
        k2_stats<<<dim3(8, QB), 256>>>(tcf, q);
        k4_A<<<dim3(8, QB), 256>>>(tcf, q);
    }
    k5_head<<<BB, 256>>>(ln1g, ln1b, W1, b1, ln2g, ln2b, W2, b2, out);
}